// round 2
// baseline (speedup 1.0000x reference)
#include <cuda_runtime.h>

// Problem:
//   encoded: (B=32, S=200, EMB=128) fp32                 -> 819200 elems
//   output_items: (B=32, T=10, K=101) int (32 or 64 bit) -> 32320 elems
//   W: (100001, 128) fp32                                -> 12800128 elems
//   b: (100001,) fp32                                    -> 100001 elems
//   out[b,t,k] = dot(encoded[b, S-T+t, :], W[items[b,t,k], :]) + bias[items[b,t,k]]

#define B_   32
#define S_   200
#define T_   10
#define K_   101
#define EMB_ 128

#define NOUT (B_ * T_ * K_)   // 32320 outputs
#define WARPS_PER_BLOCK 8
#define THREADS (WARPS_PER_BLOCK * 32)

// 1 if items buffer is int64 (little-endian: value in even word, 0 in odd word)
__device__ int g_items_is64;

// Detect dtype of items: scan odd int32 words among the first NOUT words.
// int64 data -> these are high words of items[0..NOUT/2-1], all zero.
// int32 data -> these are random indices in [0, 100001], ~never all zero.
// Reads only the first NOUT words, which is in-bounds for both layouts.
__global__ void detect_kernel(const int* __restrict__ items_i32)
{
    __shared__ int any_nonzero;
    if (threadIdx.x == 0) any_nonzero = 0;
    __syncthreads();

    int local = 0;
    for (int i = 1 + 2 * threadIdx.x; i < NOUT; i += 2 * blockDim.x)
        local |= (items_i32[i] != 0);
    if (local) atomicOr(&any_nonzero, 1);
    __syncthreads();

    if (threadIdx.x == 0)
        g_items_is64 = any_nonzero ? 0 : 1;
}

__global__ __launch_bounds__(THREADS)
void gather_dot_kernel(const float* __restrict__ enc,
                       const int* __restrict__ items_i32,
                       const float* __restrict__ W,
                       const float* __restrict__ bias,
                       float* __restrict__ out)
{
    const int gwarp = blockIdx.x * WARPS_PER_BLOCK + (threadIdx.x >> 5);
    if (gwarp >= NOUT) return;
    const int lane = threadIdx.x & 31;

    // gwarp = (b*T + t)*K + k
    const int bt = gwarp / K_;
    const int b  = bt / T_;
    const int t  = bt - b * T_;

    const int is64 = g_items_is64;
    const int idx  = is64 ? items_i32[2 * gwarp] : items_i32[gwarp];

    const float4* erow = reinterpret_cast<const float4*>(
        enc + (size_t)(b * S_ + (S_ - T_ + t)) * EMB_);
    const float4* wrow = reinterpret_cast<const float4*>(
        W + (size_t)idx * EMB_);

    const float4 e = __ldg(&erow[lane]);
    const float4 w = __ldg(&wrow[lane]);

    float s = e.x * w.x + e.y * w.y + e.z * w.z + e.w * w.w;

    #pragma unroll
    for (int o = 16; o > 0; o >>= 1)
        s += __shfl_xor_sync(0xffffffffu, s, o);

    if (lane == 0)
        out[gwarp] = s + __ldg(&bias[idx]);
}

extern "C" void kernel_launch(void* const* d_in, const int* in_sizes, int n_in,
                              void* d_out, int out_size)
{
    // Assign inputs by element count (robust to metadata ordering).
    const float* enc  = nullptr;
    const void*  itm  = nullptr;
    const float* W    = nullptr;
    const float* bias = nullptr;

    for (int i = 0; i < n_in; i++) {
        switch (in_sizes[i]) {
            case B_ * S_ * EMB_:      enc  = (const float*)d_in[i]; break;  // 819200
            case NOUT:                itm  = d_in[i];               break;  // 32320
            case 100001 * EMB_:       W    = (const float*)d_in[i]; break;  // 12800128
            case 100001:              bias = (const float*)d_in[i]; break;
            default: break;
        }
    }

    float* out = (float*)d_out;

    detect_kernel<<<1, 256>>>((const int*)itm);

    const int blocks = (NOUT + WARPS_PER_BLOCK - 1) / WARPS_PER_BLOCK;
    gather_dot_kernel<<<blocks, THREADS>>>(enc, (const int*)itm, W, bias, out);
}

// round 3
// speedup vs baseline: 1.0406x; 1.0406x over previous
#include <cuda_runtime.h>

// Problem:
//   encoded: (B=32, S=200, EMB=128) fp32                 -> 819200 elems
//   output_items: (B=32, T=10, K=101) int (32 or 64 bit) -> 32320 elems
//   W: (100001, 128) fp32                                -> 12800128 elems
//   b: (100001,) fp32                                    -> 100001 elems
//   out[b,t,k] = dot(encoded[b, S-T+t, :], W[items[b,t,k], :]) + bias[items[b,t,k]]

#define B_   32
#define S_   200
#define T_   10
#define K_   101
#define EMB_ 128

#define NOUT (B_ * T_ * K_)   // 32320 outputs
#define WARPS_PER_BLOCK 8
#define THREADS (WARPS_PER_BLOCK * 32)

// 1 if items buffer is int64 (little-endian: value in even word, 0 in odd word)
__device__ int g_items_is64;

// Detect dtype of items: scan odd int32 words among the first NOUT words.
// int64 data -> these are high words of items[0..NOUT/2-1], all zero.
// int32 data -> these are random indices in [0, 100001], ~never all zero.
// Reads only the first NOUT words, which is in-bounds for both layouts.
__global__ void detect_kernel(const int* __restrict__ items_i32)
{
    __shared__ int any_nonzero;
    if (threadIdx.x == 0) any_nonzero = 0;
    __syncthreads();

    int local = 0;
    for (int i = 1 + 2 * threadIdx.x; i < NOUT; i += 2 * blockDim.x)
        local |= (items_i32[i] != 0);
    if (local) atomicOr(&any_nonzero, 1);
    __syncthreads();

    if (threadIdx.x == 0)
        g_items_is64 = any_nonzero ? 0 : 1;
}

__global__ __launch_bounds__(THREADS)
void gather_dot_kernel(const float* __restrict__ enc,
                       const int* __restrict__ items_i32,
                       const float* __restrict__ W,
                       const float* __restrict__ bias,
                       float* __restrict__ out)
{
    const int gwarp = blockIdx.x * WARPS_PER_BLOCK + (threadIdx.x >> 5);
    if (gwarp >= NOUT) return;
    const int lane = threadIdx.x & 31;

    // gwarp = (b*T + t)*K + k
    const int bt = gwarp / K_;
    const int b  = bt / T_;
    const int t  = bt - b * T_;

    const int is64 = g_items_is64;
    const int idx  = is64 ? items_i32[2 * gwarp] : items_i32[gwarp];

    const float4* erow = reinterpret_cast<const float4*>(
        enc + (size_t)(b * S_ + (S_ - T_ + t)) * EMB_);
    const float4* wrow = reinterpret_cast<const float4*>(
        W + (size_t)idx * EMB_);

    const float4 e = __ldg(&erow[lane]);
    const float4 w = __ldg(&wrow[lane]);

    float s = e.x * w.x + e.y * w.y + e.z * w.z + e.w * w.w;

    #pragma unroll
    for (int o = 16; o > 0; o >>= 1)
        s += __shfl_xor_sync(0xffffffffu, s, o);

    if (lane == 0)
        out[gwarp] = s + __ldg(&bias[idx]);
}

extern "C" void kernel_launch(void* const* d_in, const int* in_sizes, int n_in,
                              void* d_out, int out_size)
{
    // Assign inputs by element count (robust to metadata ordering).
    const float* enc  = nullptr;
    const void*  itm  = nullptr;
    const float* W    = nullptr;
    const float* bias = nullptr;

    for (int i = 0; i < n_in; i++) {
        switch (in_sizes[i]) {
            case B_ * S_ * EMB_:      enc  = (const float*)d_in[i]; break;  // 819200
            case NOUT:                itm  = d_in[i];               break;  // 32320
            case 100001 * EMB_:       W    = (const float*)d_in[i]; break;  // 12800128
            case 100001:              bias = (const float*)d_in[i]; break;
            default: break;
        }
    }

    float* out = (float*)d_out;

    detect_kernel<<<1, 256>>>((const int*)itm);

    const int blocks = (NOUT + WARPS_PER_BLOCK - 1) / WARPS_PER_BLOCK;
    gather_dot_kernel<<<blocks, THREADS>>>(enc, (const int*)itm, W, bias, out);
}

// round 4
// speedup vs baseline: 1.0649x; 1.0234x over previous
#include <cuda_runtime.h>

// Problem:
//   encoded: (B=32, S=200, EMB=128) fp32                 -> 819200 elems
//   output_items: (B=32, T=10, K=101) int (32 or 64 bit) -> 32320 elems
//   W: (100001, 128) fp32                                -> 12800128 elems
//   b: (100001,) fp32                                    -> 100001 elems
//   out[b,t,k] = dot(encoded[b, S-T+t, :], W[items[b,t,k], :]) + bias[items[b,t,k]]

#define B_   32
#define S_   200
#define T_   10
#define K_   101
#define EMB_ 128

#define NOUT (B_ * T_ * K_)   // 32320 outputs
#define WARPS_PER_BLOCK 8
#define THREADS (WARPS_PER_BLOCK * 32)

// 1 if items buffer is int64 (little-endian: value in even word, 0 in odd word)
__device__ int g_items_is64;

// Detect dtype of items: scan odd int32 words among the first NOUT words.
// int64 data -> these are high words of items[0..NOUT/2-1], all zero.
// int32 data -> these are random indices in [0, 100001], ~never all zero.
// Reads only the first NOUT words, which is in-bounds for both layouts.
__global__ void detect_kernel(const int* __restrict__ items_i32)
{
    __shared__ int any_nonzero;
    if (threadIdx.x == 0) any_nonzero = 0;
    __syncthreads();

    int local = 0;
    for (int i = 1 + 2 * threadIdx.x; i < NOUT; i += 2 * blockDim.x)
        local |= (items_i32[i] != 0);
    if (local) atomicOr(&any_nonzero, 1);
    __syncthreads();

    if (threadIdx.x == 0)
        g_items_is64 = any_nonzero ? 0 : 1;
}

__global__ __launch_bounds__(THREADS)
void gather_dot_kernel(const float* __restrict__ enc,
                       const int* __restrict__ items_i32,
                       const float* __restrict__ W,
                       const float* __restrict__ bias,
                       float* __restrict__ out)
{
    const int gwarp = blockIdx.x * WARPS_PER_BLOCK + (threadIdx.x >> 5);
    if (gwarp >= NOUT) return;
    const int lane = threadIdx.x & 31;

    // gwarp = (b*T + t)*K + k
    const int bt = gwarp / K_;
    const int b  = bt / T_;
    const int t  = bt - b * T_;

    const int is64 = g_items_is64;
    const int idx  = is64 ? items_i32[2 * gwarp] : items_i32[gwarp];

    const float4* erow = reinterpret_cast<const float4*>(
        enc + (size_t)(b * S_ + (S_ - T_ + t)) * EMB_);
    const float4* wrow = reinterpret_cast<const float4*>(
        W + (size_t)idx * EMB_);

    const float4 e = __ldg(&erow[lane]);
    const float4 w = __ldg(&wrow[lane]);

    float s = e.x * w.x + e.y * w.y + e.z * w.z + e.w * w.w;

    #pragma unroll
    for (int o = 16; o > 0; o >>= 1)
        s += __shfl_xor_sync(0xffffffffu, s, o);

    if (lane == 0)
        out[gwarp] = s + __ldg(&bias[idx]);
}

extern "C" void kernel_launch(void* const* d_in, const int* in_sizes, int n_in,
                              void* d_out, int out_size)
{
    // Assign inputs by element count (robust to metadata ordering).
    const float* enc  = nullptr;
    const void*  itm  = nullptr;
    const float* W    = nullptr;
    const float* bias = nullptr;

    for (int i = 0; i < n_in; i++) {
        switch (in_sizes[i]) {
            case B_ * S_ * EMB_:      enc  = (const float*)d_in[i]; break;  // 819200
            case NOUT:                itm  = d_in[i];               break;  // 32320
            case 100001 * EMB_:       W    = (const float*)d_in[i]; break;  // 12800128
            case 100001:              bias = (const float*)d_in[i]; break;
            default: break;
        }
    }

    float* out = (float*)d_out;

    detect_kernel<<<1, 256>>>((const int*)itm);

    const int blocks = (NOUT + WARPS_PER_BLOCK - 1) / WARPS_PER_BLOCK;
    gather_dot_kernel<<<blocks, THREADS>>>(enc, (const int*)itm, W, bias, out);
}